// round 2
// baseline (speedup 1.0000x reference)
#include <cuda_runtime.h>
#include <stdint.h>

#define BW 4096
#define P_C 16769025u   // 4095*4095
#define P_E 16760836u   // 4094*4094

__global__ void __launch_bounds__(256, 4)
motif_kernel(const int* __restrict__ board, float* __restrict__ out)
{
    const int i  = blockIdx.x;      // output row, 0..4094
    const int t  = threadIdx.x;     // 0..255
    const int c0 = t << 4;          // window start col; window = cols c0..c0+23

    // ---- Build 24-bit bitmasks for board rows i, i+1, i+2 ----
    uint32_t b[3], w[3];
#pragma unroll
    for (int r = 0; r < 3; ++r) {
        uint32_t bb = 0, ww = 0;
        const int* rp = board + (size_t)(i + r) * BW;
        const bool rowok = (i + r) < BW;        // false only for i==4094, r==2
#pragma unroll
        for (int k = 0; k < 6; ++k) {
            const int col = c0 + 4 * k;
            if (rowok && col < BW) {            // col check fails only for t==255, k>=4
                int4 v = *reinterpret_cast<const int4*>(rp + col);
                uint32_t pw = (uint32_t)v.x | ((uint32_t)v.y << 8)
                            | ((uint32_t)v.z << 16) | ((uint32_t)v.w << 24);
                uint32_t bn = ((pw & 0x01010101u) * 0x01020408u) >> 24;         // black bits
                uint32_t wn = (((pw >> 1) & 0x01010101u) * 0x01020408u) >> 24;  // white bits
                bb |= bn << (4 * k);
                ww |= wn << (4 * k);
            }
        }
        b[r] = bb; w[r] = ww;
    }

    const uint32_t e0 = ~(b[0] | w[0]);
    const uint32_t e1 = ~(b[1] | w[1]);
    const uint32_t anyE = e0 | (e0 >> 1) | e1 | (e1 >> 1);

    // bit c of plane <-> output col c0+c.  Corners: A=(i,c) B=(i,c+1) C=(i+1,c) D=(i+1,c+1)
    uint32_t planes[8];
    {   // black
        uint32_t A = b[0], B = b[0] >> 1, C = b[1], D = b[1] >> 1;
        uint32_t AB = A & B, CD = C & D, AD = A & D, BC = B & C;
        uint32_t ge2 = AB | CD | AD | BC | (A & C) | (B & D);
        uint32_t ge3 = (AB & (C | D)) | (CD & (A | B));
        uint32_t eq4 = AB & CD;
        planes[0] = (AD & (e0 >> 1) & e1) | (BC & e0 & (e1 >> 1));   // bamboo_black
        planes[2] = ge2 & anyE;                                      // tiger_black
        planes[4] = ge3 & ~eq4 & anyE;                               // empty_triangle_black
        planes[6] = (e1 >> 1) & (b[0] >> 1) & (b[2] >> 1) & b[1] & (b[1] >> 2); // eye_black
    }
    {   // white
        uint32_t A = w[0], B = w[0] >> 1, C = w[1], D = w[1] >> 1;
        uint32_t AB = A & B, CD = C & D, AD = A & D, BC = B & C;
        uint32_t ge2 = AB | CD | AD | BC | (A & C) | (B & D);
        uint32_t ge3 = (AB & (C | D)) | (CD & (A | B));
        uint32_t eq4 = AB & CD;
        planes[1] = (AD & (e0 >> 1) & e1) | (BC & e0 & (e1 >> 1));   // bamboo_white
        planes[3] = ge2 & anyE;                                      // tiger_white
        planes[5] = ge3 & ~eq4 & anyE;                               // empty_triangle_white
        planes[7] = (e1 >> 1) & (w[0] >> 1) & (w[2] >> 1) & w[1] & (w[1] >> 2); // eye_white
    }

    // ---- Store: float32 output, aligned float4 body + scalar head/tail ----
#pragma unroll
    for (int p = 0; p < 8; ++p) {
        int rw; size_t gb;
        if (p < 6) {
            rw = 4095;
            gb = (size_t)p * P_C + (size_t)i * 4095u;
        } else {
            if (i >= 4094) break;   // eye planes have only 4094 rows
            rw = 4094;
            gb = 6 * (size_t)P_C + (size_t)(p - 6) * P_E + (size_t)i * 4094u;
        }
        const int s  = (int)(gb & 3);       // row start misalignment (floats)
        const int h  = (4 - s) & 3;         // scalar head floats (cols 0..h-1)
        const int Nv = (rw - h) >> 2;       // aligned float4 vectors in row
        const uint32_t m = planes[p];
        float* gp = out + gb;

        if (t == 0) {
            for (int c = 0; c < h; ++c)
                gp[c] = (float)((m >> c) & 1u);
        }
#pragma unroll
        for (int q = 0; q < 4; ++q) {
            const int vi = (t << 2) + q;    // vector index; col = h + 4*vi
            if (vi < Nv) {
                const uint32_t nib = (m >> (h + 4 * q)) & 0xFu;  // bits for cols h+16t+4q..+3
                float4 v;
                v.x = __uint_as_float((nib & 1u)        * 0x3F800000u);
                v.y = __uint_as_float(((nib >> 1) & 1u) * 0x3F800000u);
                v.z = __uint_as_float(((nib >> 2) & 1u) * 0x3F800000u);
                v.w = __uint_as_float(((nib >> 3) & 1u) * 0x3F800000u);
                *reinterpret_cast<float4*>(gp + h + (vi << 2)) = v;  // 16B-aligned
            }
        }
        if (t == 255) {   // tail cols h+4*Nv .. rw-1 (0..3 floats), bits (col-4080)
            for (int c = h + (Nv << 2); c < rw; ++c)
                gp[c] = (float)((m >> (c - 4080)) & 1u);
        }
    }
}

extern "C" void kernel_launch(void* const* d_in, const int* in_sizes, int n_in,
                              void* d_out, int out_size)
{
    const int* board = (const int*)d_in[0];
    float* out = (float*)d_out;
    motif_kernel<<<4095, 256>>>(board, out);
}

// round 3
// speedup vs baseline: 1.6710x; 1.6710x over previous
#include <cuda_runtime.h>
#include <stdint.h>

#define BW 4096
#define P_C 16769025u   // 4095*4095
#define P_E 16760836u   // 4094*4094
#define ROWS 4          // output rows per block

__global__ void __launch_bounds__(256, 4)
motif_kernel(const int* __restrict__ board, float* __restrict__ out)
{
    __shared__ uint32_t smask[8][256];

    const int i0 = blockIdx.x * ROWS;   // first output row of this block
    const int t  = threadIdx.x;         // 0..255
    const int c0 = t << 4;              // window start col; window = cols c0..c0+23

    // ---- Build 24-bit bitmasks for board rows i0 .. i0+ROWS+1 ----
    uint32_t b[ROWS + 2], w[ROWS + 2];
#pragma unroll
    for (int r = 0; r < ROWS + 2; ++r) {
        uint32_t bb = 0, ww = 0;
        const int* rp = board + (size_t)(i0 + r) * BW;
        const bool rowok = (i0 + r) < BW;
#pragma unroll
        for (int k = 0; k < 6; ++k) {
            const int col = c0 + 4 * k;
            if (rowok && col < BW) {
                int4 v = *reinterpret_cast<const int4*>(rp + col);
                uint32_t pw = (uint32_t)v.x | ((uint32_t)v.y << 8)
                            | ((uint32_t)v.z << 16) | ((uint32_t)v.w << 24);
                uint32_t bn = ((pw & 0x01010101u) * 0x01020408u) >> 24;
                uint32_t wn = (((pw >> 1) & 0x01010101u) * 0x01020408u) >> 24;
                bb |= bn << (4 * k);
                ww |= wn << (4 * k);
            }
        }
        b[r] = bb; w[r] = ww;
    }

#pragma unroll
    for (int ro = 0; ro < ROWS; ++ro) {
        const int i = i0 + ro;
        if (i >= 4095) break;

        const uint32_t e0 = ~(b[ro] | w[ro]);
        const uint32_t e1 = ~(b[ro + 1] | w[ro + 1]);
        const uint32_t anyE = e0 | (e0 >> 1) | e1 | (e1 >> 1);

        // Corners for col c: A=(i,c) B=(i,c+1) C=(i+1,c) D=(i+1,c+1)
        {   // black
            uint32_t A = b[ro], B = b[ro] >> 1, C = b[ro + 1], D = b[ro + 1] >> 1;
            uint32_t AB = A & B, CD = C & D, AD = A & D, BC = B & C;
            uint32_t ge2 = AB | CD | AD | BC | (A & C) | (B & D);
            uint32_t ge3 = (AB & (C | D)) | (CD & (A | B));
            uint32_t eq4 = AB & CD;
            smask[0][t] = (AD & (e0 >> 1) & e1) | (BC & e0 & (e1 >> 1));     // bamboo_b
            smask[2][t] = ge2 & anyE;                                        // tiger_b
            smask[4][t] = ge3 & ~eq4 & anyE;                                 // triangle_b
            smask[6][t] = (e1 >> 1) & (b[ro] >> 1) & (b[ro + 2] >> 1)
                        & b[ro + 1] & (b[ro + 1] >> 2);                      // eye_b
        }
        {   // white
            uint32_t A = w[ro], B = w[ro] >> 1, C = w[ro + 1], D = w[ro + 1] >> 1;
            uint32_t AB = A & B, CD = C & D, AD = A & D, BC = B & C;
            uint32_t ge2 = AB | CD | AD | BC | (A & C) | (B & D);
            uint32_t ge3 = (AB & (C | D)) | (CD & (A | B));
            uint32_t eq4 = AB & CD;
            smask[1][t] = (AD & (e0 >> 1) & e1) | (BC & e0 & (e1 >> 1));     // bamboo_w
            smask[3][t] = ge2 & anyE;                                        // tiger_w
            smask[5][t] = ge3 & ~eq4 & anyE;                                 // triangle_w
            smask[7][t] = (e1 >> 1) & (w[ro] >> 1) & (w[ro + 2] >> 1)
                        & w[ro + 1] & (w[ro + 1] >> 2);                      // eye_w
        }
        __syncthreads();

        // ---- Coalesced stores: lane t writes vector 256*q + t (contiguous lanes) ----
#pragma unroll
        for (int p = 0; p < 8; ++p) {
            int rw; size_t gb;
            if (p < 6) {
                rw = 4095;
                gb = (size_t)p * P_C + (size_t)i * 4095u;
            } else {
                if (i >= 4094) break;    // eye planes: 4094 rows
                rw = 4094;
                gb = 6 * (size_t)P_C + (size_t)(p - 6) * P_E + (size_t)i * 4094u;
            }
            const int h  = (4 - (int)(gb & 3)) & 3;   // scalar head floats
            const int Nv = (rw - h) >> 2;             // aligned float4 count
            float* gp = out + gb;

            if (t == 0)
                for (int c = 0; c < h; ++c)
                    gp[c] = (float)((smask[p][0] >> c) & 1u);
#pragma unroll
            for (int q = 0; q < 4; ++q) {
                const int vi = (q << 8) + t;          // lanes contiguous -> coalesced
                if (vi < Nv) {
                    const int cb = h + (vi << 2);     // first col of this vector
                    const uint32_t nib = (smask[p][cb >> 4] >> (cb & 15)) & 0xFu;
                    float4 v;
                    v.x = __uint_as_float((nib & 1u)        * 0x3F800000u);
                    v.y = __uint_as_float(((nib >> 1) & 1u) * 0x3F800000u);
                    v.z = __uint_as_float(((nib >> 2) & 1u) * 0x3F800000u);
                    v.w = __uint_as_float(((nib >> 3) & 1u) * 0x3F800000u);
                    *reinterpret_cast<float4*>(gp + cb) = v;
                }
            }
            if (t == 255)    // tail: cols h+4*Nv .. rw-1, bits relative to owner 255
                for (int c = h + (Nv << 2); c < rw; ++c)
                    gp[c] = (float)((smask[p][255] >> (c - 4080)) & 1u);
        }
        __syncthreads();   // protect smask before next row overwrites
    }
}

extern "C" void kernel_launch(void* const* d_in, const int* in_sizes, int n_in,
                              void* d_out, int out_size)
{
    const int* board = (const int*)d_in[0];
    float* out = (float*)d_out;
    motif_kernel<<<(4095 + ROWS - 1) / ROWS, 256>>>(board, out);
}